// round 1
// baseline (speedup 1.0000x reference)
#include <cuda_runtime.h>
#include <math.h>

#define NANCH 896
#define MAXDET 64
#define NT 256

__global__ __launch_bounds__(NT) void blazeface_nms_kernel(
    const float* __restrict__ raw_boxes,
    const float* __restrict__ raw_scores,
    const float* __restrict__ anchors,
    const float* __restrict__ tmat,
    const int* __restrict__ hp,
    const int* __restrict__ wp,
    float* __restrict__ out)
{
    extern __shared__ float sm[];
    float* cbox = sm;               // [NANCH*17] decoded coords (+score in slot 16)
    float* rem  = cbox + NANCH*17;  // [NANCH]
    float* csc  = rem + NANCH;      // [NANCH]

    __shared__ float s_part[8][17];
    __shared__ float s_bval[8];
    __shared__ int   s_bidx[8];
    __shared__ int   s_wcnt[8];
    __shared__ int   s_nc;
    __shared__ float s_det[17];
    __shared__ float s_bestval;
    __shared__ int   s_best;
    __shared__ float s_m[8];

    const int b    = blockIdx.x;
    const int tid  = threadIdx.x;
    const int lane = tid & 31;
    const int wid  = tid >> 5;

    if (tid == 0) s_nc = 0;
    if (tid < 8)  s_m[tid] = tmat[b*8 + tid];
    const float hf = (float)(*hp);
    const float wf = (float)(*wp);
    __syncthreads();

    const float* rb = raw_boxes  + (size_t)b * (NANCH*16);
    const float* rs = raw_scores + (size_t)b * NANCH;

    // ---- decode + stable compaction of candidates (score >= 0.5) ----
    for (int base = 0; base < NANCH; base += NT) {
        int a = base + tid;
        bool pred = false;
        float sc = 0.f;
        if (a < NANCH) {
            float x = rs[a];
            x = fminf(fmaxf(x, -100.f), 100.f);
            sc = 1.f / (1.f + expf(-x));
            pred = (sc >= 0.5f);
        }
        unsigned mask = __ballot_sync(0xffffffffu, pred);
        if (lane == 0) s_wcnt[wid] = __popc(mask);
        __syncthreads();
        int off = s_nc;
        #pragma unroll
        for (int k = 0; k < 8; k++) if (k < wid) off += s_wcnt[k];
        off += __popc(mask & ((1u << lane) - 1u));
        if (pred) {
            const float4* r4 = (const float4*)(rb + a*16);
            float4 p0 = r4[0], p1 = r4[1], p2 = r4[2], p3 = r4[3];
            float ax = anchors[a*4+0], ay = anchors[a*4+1];
            float aw = anchors[a*4+2], ah = anchors[a*4+3];
            const float inv = 0.0078125f;  // 1/128
            float xc = p0.x*inv*aw + ax;
            float yc = p0.y*inv*ah + ay;
            float bw = p0.z*inv*aw;
            float bh = p0.w*inv*ah;
            float* c = cbox + off*17;
            c[0]  = yc - bh*0.5f;
            c[1]  = xc - bw*0.5f;
            c[2]  = yc + bh*0.5f;
            c[3]  = xc + bw*0.5f;
            c[4]  = p1.x*inv*aw + ax;  c[5]  = p1.y*inv*ah + ay;
            c[6]  = p1.z*inv*aw + ax;  c[7]  = p1.w*inv*ah + ay;
            c[8]  = p2.x*inv*aw + ax;  c[9]  = p2.y*inv*ah + ay;
            c[10] = p2.z*inv*aw + ax;  c[11] = p2.w*inv*ah + ay;
            c[12] = p3.x*inv*aw + ax;  c[13] = p3.y*inv*ah + ay;
            c[14] = p3.z*inv*aw + ax;  c[15] = p3.w*inv*ah + ay;
            c[16] = sc;
            csc[off] = sc;
            rem[off] = sc;
        }
        __syncthreads();
        if (tid == 0) {
            int t = 0;
            #pragma unroll
            for (int k = 0; k < 8; k++) t += s_wcnt[k];
            s_nc += t;
        }
        __syncthreads();
    }

    const int nc = s_nc;
    float* obase = out + (size_t)b * (MAXDET*17);

    // ---- 64 sequential NMS steps ----
    for (int it = 0; it < MAXDET; it++) {
        // argmax with first-index tie-break (matches jnp.argmax)
        float bv = -1e30f; int bi = 0x7fffffff;
        for (int i = tid; i < nc; i += NT) {
            float v = rem[i];
            if (v > bv) { bv = v; bi = i; }   // strided: lower i seen first per thread
        }
        #pragma unroll
        for (int o = 16; o > 0; o >>= 1) {
            float ov = __shfl_down_sync(0xffffffffu, bv, o);
            int   oi = __shfl_down_sync(0xffffffffu, bi, o);
            if (ov > bv || (ov == bv && oi < bi)) { bv = ov; bi = oi; }
        }
        if (lane == 0) { s_bval[wid] = bv; s_bidx[wid] = bi; }
        __syncthreads();
        if (tid == 0) {
            float v = s_bval[0]; int ix = s_bidx[0];
            #pragma unroll
            for (int k = 1; k < 8; k++) {
                if (s_bval[k] > v || (s_bval[k] == v && s_bidx[k] < ix)) {
                    v = s_bval[k]; ix = s_bidx[k];
                }
            }
            s_bestval = v; s_best = ix;
        }
        __syncthreads();
        float best = s_bestval;
        if (best <= 0.f) {
            // reference emits exact zeros for all remaining detections
            for (int j = it*17 + tid; j < MAXDET*17; j += NT) obase[j] = 0.f;
            return;
        }
        int bix = s_best;
        float b0 = cbox[bix*17+0], b1 = cbox[bix*17+1];
        float b2 = cbox[bix*17+2], b3 = cbox[bix*17+3];
        float a1 = fmaxf(b2-b0, 0.f) * fmaxf(b3-b1, 0.f);

        float acc[17];
        #pragma unroll
        for (int k = 0; k < 17; k++) acc[k] = 0.f;
        for (int i = tid; i < nc; i += NT) {
            float r = rem[i];
            if (r > 0.f) {
                const float* c = cbox + i*17;
                float c0 = c[0], c1 = c[1], c2 = c[2], c3 = c[3];
                float ymin = fmaxf(b0, c0), xmin = fmaxf(b1, c1);
                float ymax = fminf(b2, c2), xmax = fminf(b3, c3);
                float inter = fmaxf(ymax-ymin, 0.f) * fmaxf(xmax-xmin, 0.f);
                float a2 = fmaxf(c2-c0, 0.f) * fmaxf(c3-c1, 0.f);
                float iou = inter / fmaxf(a1 + a2 - inter, 1e-6f);
                if (iou > 0.3f) {
                    float ws = csc[i];
                    #pragma unroll
                    for (int k = 0; k < 16; k++) acc[k] += c[k]*ws;
                    acc[16] += ws;
                    rem[i] = -1.f;
                }
            }
        }
        #pragma unroll
        for (int k = 0; k < 17; k++) {
            #pragma unroll
            for (int o = 16; o > 0; o >>= 1)
                acc[k] += __shfl_down_sync(0xffffffffu, acc[k], o);
        }
        if (lane == 0) {
            #pragma unroll
            for (int k = 0; k < 17; k++) s_part[wid][k] = acc[k];
        }
        __syncthreads();
        if (tid < 17) {
            float s = 0.f;
            #pragma unroll
            for (int w = 0; w < 8; w++) s += s_part[w][tid];
            s_det[tid] = s;
        }
        __syncthreads();
        // fused projection + rescale on write-out
        float* o = obase + it*17;
        if (tid < 8) {
            const int xi[8] = {1,3,4,6,8,10,12,14};
            const int yi[8] = {0,2,5,7,9,11,13,15};
            float denom = fmaxf(s_det[16], 1e-6f);
            float x = s_det[xi[tid]] / denom;
            float y = s_det[yi[tid]] / denom;
            float nx = x*s_m[0] + y*s_m[1] + s_m[3];
            float ny = x*s_m[4] + y*s_m[5] + s_m[7];
            o[xi[tid]] = nx * wf;
            o[yi[tid]] = ny * hf;
        } else if (tid == 8) {
            o[16] = best;
        }
        __syncthreads();
    }
}

extern "C" void kernel_launch(void* const* d_in, const int* in_sizes, int n_in,
                              void* d_out, int out_size) {
    const float* raw_boxes  = (const float*)d_in[0];
    const float* raw_scores = (const float*)d_in[1];
    const float* anchors    = (const float*)d_in[2];
    const float* tmat       = (const float*)d_in[3];
    const int*   hp         = (const int*)d_in[4];
    const int*   wp         = (const int*)d_in[5];
    float* out = (float*)d_out;

    int B = in_sizes[1] / NANCH;  // raw_scores element count / 896
    size_t smem = (size_t)(NANCH*17 + NANCH + NANCH) * sizeof(float);
    cudaFuncSetAttribute(blazeface_nms_kernel,
                         cudaFuncAttributeMaxDynamicSharedMemorySize, (int)smem);
    blazeface_nms_kernel<<<B, NT, smem>>>(raw_boxes, raw_scores, anchors, tmat,
                                          hp, wp, out);
}

// round 2
// speedup vs baseline: 1.3205x; 1.3205x over previous
#include <cuda_runtime.h>
#include <math.h>

#define NANCH 896
#define MAXDET 64
#define NT 256
#define SLOTS 4   // ceil(NANCH / NT)

__global__ __launch_bounds__(NT, 4) void blazeface_nms_kernel(
    const float* __restrict__ raw_boxes,
    const float* __restrict__ raw_scores,
    const float* __restrict__ anchors,
    const float* __restrict__ tmat,
    const int* __restrict__ hp,
    const int* __restrict__ wp,
    float* __restrict__ out)
{
    extern __shared__ float cbox[];   // [NANCH * 16] compacted decoded coords

    __shared__ float s_acc[17];
    __shared__ float s_bval[8];
    __shared__ int   s_bidx[8];
    __shared__ int   s_wcnt[SLOTS][8];
    __shared__ float s_bestval;
    __shared__ int   s_best;
    __shared__ float s_m[8];

    const int b    = blockIdx.x;
    const int tid  = threadIdx.x;
    const int lane = tid & 31;
    const int wid  = tid >> 5;

    if (tid < 8) s_m[tid] = tmat[b*8 + tid];
    const float hf = (float)(*hp);
    const float wf = (float)(*wp);

    const float* rb = raw_boxes  + (size_t)b * (NANCH*16);
    const float* rs = raw_scores + (size_t)b * NANCH;

    // ---- phase 1: score + ballot for stable compaction ----
    bool  pred[SLOTS];
    float sc[SLOTS];
    unsigned mk[SLOTS];
    #pragma unroll
    for (int j = 0; j < SLOTS; j++) {
        int a = j*NT + tid;
        pred[j] = false; sc[j] = 0.f;
        if (a < NANCH) {
            float x = rs[a];
            x = fminf(fmaxf(x, -100.f), 100.f);
            float s = 1.f / (1.f + expf(-x));
            sc[j] = s;
            pred[j] = (s >= 0.5f);
        }
        mk[j] = __ballot_sync(0xffffffffu, pred[j]);
        if (lane == 0) s_wcnt[j][wid] = __popc(mk[j]);
    }
    __syncthreads();

    // prefix offsets (global candidate order = anchor order)
    int tot[SLOTS], wbase[SLOTS];
    #pragma unroll
    for (int j = 0; j < SLOTS; j++) {
        int t = 0, wb = 0;
        #pragma unroll
        for (int w = 0; w < 8; w++) {
            int c = s_wcnt[j][w];
            t += c;
            if (w < wid) wb += c;
        }
        tot[j] = t; wbase[j] = wb;
    }

    // ---- phase 2: decode owned candidates; box+score+rem in registers ----
    int   idx[SLOTS];
    float rem[SLOTS];
    float by0[SLOTS], bx0[SLOTS], by1[SLOTS], bx1[SLOTS];
    #pragma unroll
    for (int j = 0; j < SLOTS; j++) {
        idx[j] = 0x7fffffff;
        rem[j] = -1.f;
        by0[j] = bx0[j] = by1[j] = bx1[j] = 0.f;
        if (pred[j]) {
            int off = __popc(mk[j] & ((1u << lane) - 1u)) + wbase[j];
            #pragma unroll
            for (int jp = 0; jp < SLOTS; jp++) if (jp < j) off += tot[jp];
            int a = j*NT + tid;
            const float4* r4 = (const float4*)(rb + a*16);
            float4 p0 = r4[0], p1 = r4[1], p2 = r4[2], p3 = r4[3];
            float4 an = ((const float4*)anchors)[a];
            float ax = an.x, ay = an.y, aw = an.z, ah = an.w;
            const float inv = 0.0078125f;
            float xc = p0.x*inv*aw + ax;
            float yc = p0.y*inv*ah + ay;
            float bw = p0.z*inv*aw;
            float bh = p0.w*inv*ah;
            float c0 = yc - bh*0.5f, c1 = xc - bw*0.5f;
            float c2 = yc + bh*0.5f, c3 = xc + bw*0.5f;
            by0[j] = c0; bx0[j] = c1; by1[j] = c2; bx1[j] = c3;
            idx[j] = off;
            rem[j] = sc[j];
            float4* w4 = (float4*)(cbox + off*16);
            w4[0] = make_float4(c0, c1, c2, c3);
            w4[1] = make_float4(p1.x*inv*aw + ax, p1.y*inv*ah + ay,
                                p1.z*inv*aw + ax, p1.w*inv*ah + ay);
            w4[2] = make_float4(p2.x*inv*aw + ax, p2.y*inv*ah + ay,
                                p2.z*inv*aw + ax, p2.w*inv*ah + ay);
            w4[3] = make_float4(p3.x*inv*aw + ax, p3.y*inv*ah + ay,
                                p3.z*inv*aw + ax, p3.w*inv*ah + ay);
        }
    }
    __syncthreads();

    float* obase = out + (size_t)b * (MAXDET*17);

    // ---- phase 3: 64 sequential NMS steps, register-resident hot loop ----
    for (int it = 0; it < MAXDET; it++) {
        // local argmax with first-index tie-break
        float bv = -1.f; int bi = 0x7fffffff;
        #pragma unroll
        for (int j = 0; j < SLOTS; j++) {
            if (rem[j] > bv) { bv = rem[j]; bi = idx[j]; }  // idx increasing in j
        }
        #pragma unroll
        for (int o = 16; o > 0; o >>= 1) {
            float ov = __shfl_down_sync(0xffffffffu, bv, o);
            int   oi = __shfl_down_sync(0xffffffffu, bi, o);
            if (ov > bv || (ov == bv && oi < bi)) { bv = ov; bi = oi; }
        }
        if (lane == 0) { s_bval[wid] = bv; s_bidx[wid] = bi; }
        __syncthreads();
        if (tid == 0) {
            float v = s_bval[0]; int ix = s_bidx[0];
            #pragma unroll
            for (int k = 1; k < 8; k++) {
                if (s_bval[k] > v || (s_bval[k] == v && s_bidx[k] < ix)) {
                    v = s_bval[k]; ix = s_bidx[k];
                }
            }
            s_bestval = v; s_best = ix;
        }
        if (tid >= 32 && tid < 49) s_acc[tid - 32] = 0.f;  // warp 1 resets accumulator
        __syncthreads();

        float best = s_bestval;
        if (best <= 0.f) {
            for (int k = it*17 + tid; k < MAXDET*17; k += NT) obase[k] = 0.f;
            return;
        }
        int bix = s_best;
        float q0 = cbox[bix*16+0], q1 = cbox[bix*16+1];
        float q2 = cbox[bix*16+2], q3 = cbox[bix*16+3];
        float a1 = fmaxf(q2-q0, 0.f) * fmaxf(q3-q1, 0.f);

        #pragma unroll
        for (int j = 0; j < SLOTS; j++) {
            if (rem[j] > 0.f) {
                float ymin = fmaxf(q0, by0[j]), xmin = fmaxf(q1, bx0[j]);
                float ymax = fminf(q2, by1[j]), xmax = fminf(q3, bx1[j]);
                float inter = fmaxf(ymax-ymin, 0.f) * fmaxf(xmax-xmin, 0.f);
                float a2 = fmaxf(by1[j]-by0[j], 0.f) * fmaxf(bx1[j]-bx0[j], 0.f);
                float iou = inter / fmaxf(a1 + a2 - inter, 1e-6f);
                if (iou > 0.3f) {
                    rem[j] = -1.f;
                    float w = sc[j];
                    atomicAdd(&s_acc[0],  by0[j]*w);
                    atomicAdd(&s_acc[1],  bx0[j]*w);
                    atomicAdd(&s_acc[2],  by1[j]*w);
                    atomicAdd(&s_acc[3],  bx1[j]*w);
                    const float* c = cbox + idx[j]*16;
                    #pragma unroll
                    for (int k = 4; k < 16; k++) atomicAdd(&s_acc[k], c[k]*w);
                    atomicAdd(&s_acc[16], w);
                }
            }
        }
        __syncthreads();

        // fused projection + rescale on write-out (warp 0)
        float* o = obase + it*17;
        if (tid < 8) {
            const int xi[8] = {1,3,4,6,8,10,12,14};
            const int yi[8] = {0,2,5,7,9,11,13,15};
            float denom = fmaxf(s_acc[16], 1e-6f);
            float x = s_acc[xi[tid]] / denom;
            float y = s_acc[yi[tid]] / denom;
            float nx = x*s_m[0] + y*s_m[1] + s_m[3];
            float ny = x*s_m[4] + y*s_m[5] + s_m[7];
            o[xi[tid]] = nx * wf;
            o[yi[tid]] = ny * hf;
        } else if (tid == 8) {
            o[16] = best;
        }
    }
}

extern "C" void kernel_launch(void* const* d_in, const int* in_sizes, int n_in,
                              void* d_out, int out_size) {
    const float* raw_boxes  = (const float*)d_in[0];
    const float* raw_scores = (const float*)d_in[1];
    const float* anchors    = (const float*)d_in[2];
    const float* tmat       = (const float*)d_in[3];
    const int*   hp         = (const int*)d_in[4];
    const int*   wp         = (const int*)d_in[5];
    float* out = (float*)d_out;

    int B = in_sizes[1] / NANCH;
    size_t smem = (size_t)(NANCH * 16) * sizeof(float);
    cudaFuncSetAttribute(blazeface_nms_kernel,
                         cudaFuncAttributeMaxDynamicSharedMemorySize, (int)smem);
    blazeface_nms_kernel<<<B, NT, smem>>>(raw_boxes, raw_scores, anchors, tmat,
                                          hp, wp, out);
}